// round 6
// baseline (speedup 1.0000x reference)
#include <cuda_runtime.h>

// QuantizedAdd via per-block float LUTs, near-single-wave persistent grid.
// out = clamp(lut1f[bypass] + lut2f[prev], -128, 127)  (float adds/clamps on
// FMA pipe; LUT entries exact in fp32, so result is bit-exact vs reference).
// Output buffer is float32 (established R4).

#define THREADS 256
#define GX 9   // grid = GX x B = 1152 blocks ~ 148 SMs * 8 CTAs (one wave)

__device__ __forceinline__ int rq(int x, int z, int lsh, int M0,
                                  unsigned mask, int thr_base, int rsh)
{
    int d = (x - z) << lsh;
    long long nudge = (d >= 0) ? (1LL << 30) : (1LL - (1LL << 30));
    long long prod = (long long)d * (long long)M0 + nudge;   // IMAD.WIDE
    int v = (int)(prod >> 31);                               // |v| <= 1020
    unsigned rem = (unsigned)v & mask;
    unsigned thr = (unsigned)(thr_base + (v < 0 ? 1 : 0));
    return (v >> rsh) + (rem > thr ? 1 : 0);
}

__global__ void __launch_bounds__(THREADS)
qadd_kernel(const int4* __restrict__ bypass,
            const int4* __restrict__ prev,
            const int* __restrict__ batch_cluster,
            const int* __restrict__ z_bypass,
            const int* __restrict__ z_prev,
            const int* __restrict__ z3_arr,
            const int* __restrict__ M0_bypass,
            const int* __restrict__ M0_prev,
            const int* __restrict__ shift_bypass,
            const int* __restrict__ shift_prev,
            float4* __restrict__ out,
            int nv4)   // (C*H*W)/4 per sample
{
    __shared__ float lut1[256];
    __shared__ float lut2[256];

    const int b = blockIdx.y;
    const int t = threadIdx.x;

    // ---- build LUTs once per block ----
    {
        const int c  = __ldg(&batch_cluster[b]);
        const int z1 = __ldg(&z_bypass[c]);
        const int z2 = __ldg(&z_prev[c]);
        const int z3 = __ldg(&z3_arr[c]);
        const int M1 = __ldg(&M0_bypass[c]);
        const int M2 = __ldg(&M0_prev[c]);
        const int s1 = __ldg(&shift_bypass[c]);
        const int s2 = __ldg(&shift_prev[c]);

        const int lsh1 = s1 < 0 ? -s1 : 0;
        const int rsh1 = s1 < 0 ? 0 : s1;
        const int lsh2 = s2 < 0 ? -s2 : 0;
        const int rsh2 = s2 < 0 ? 0 : s2;
        const unsigned mask1 = (1u << rsh1) - 1u;
        const unsigned mask2 = (1u << rsh2) - 1u;

        lut1[t] = (float)(rq(t, z1, lsh1, M1, mask1, (int)(mask1 >> 1), rsh1) + z3);
        lut2[t] = (float)(rq(t, z2, lsh2, M2, mask2, (int)(mask2 >> 1), rsh2));
    }
    __syncthreads();

    const size_t sbase = (size_t)b * (size_t)nv4;
    const int stride = GX * THREADS;               // 2304

    int i = blockIdx.x * THREADS + t;

    // unroll-by-2 main loop: both iterations' loads issued up front (MLP=4)
    for (; i + stride < nv4; i += 2 * stride) {
        const int4 xb0 = __ldcs(&bypass[sbase + i]);
        const int4 xp0 = __ldcs(&prev  [sbase + i]);
        const int4 xb1 = __ldcs(&bypass[sbase + i + stride]);
        const int4 xp1 = __ldcs(&prev  [sbase + i + stride]);

        float4 o0, o1;
        o0.x = fmaxf(-128.f, fminf(127.f, lut1[xb0.x] + lut2[xp0.x]));
        o0.y = fmaxf(-128.f, fminf(127.f, lut1[xb0.y] + lut2[xp0.y]));
        o0.z = fmaxf(-128.f, fminf(127.f, lut1[xb0.z] + lut2[xp0.z]));
        o0.w = fmaxf(-128.f, fminf(127.f, lut1[xb0.w] + lut2[xp0.w]));
        o1.x = fmaxf(-128.f, fminf(127.f, lut1[xb1.x] + lut2[xp1.x]));
        o1.y = fmaxf(-128.f, fminf(127.f, lut1[xb1.y] + lut2[xp1.y]));
        o1.z = fmaxf(-128.f, fminf(127.f, lut1[xb1.z] + lut2[xp1.z]));
        o1.w = fmaxf(-128.f, fminf(127.f, lut1[xb1.w] + lut2[xp1.w]));

        __stcs(&out[sbase + i], o0);
        __stcs(&out[sbase + i + stride], o1);
    }
    if (i < nv4) {
        const int4 xb = __ldcs(&bypass[sbase + i]);
        const int4 xp = __ldcs(&prev  [sbase + i]);
        float4 o;
        o.x = fmaxf(-128.f, fminf(127.f, lut1[xb.x] + lut2[xp.x]));
        o.y = fmaxf(-128.f, fminf(127.f, lut1[xb.y] + lut2[xp.y]));
        o.z = fmaxf(-128.f, fminf(127.f, lut1[xb.z] + lut2[xp.z]));
        o.w = fmaxf(-128.f, fminf(127.f, lut1[xb.w] + lut2[xp.w]));
        __stcs(&out[sbase + i], o);
    }
}

extern "C" void kernel_launch(void* const* d_in, const int* in_sizes, int n_in,
                              void* d_out, int out_size)
{
    // ---- resolve input mapping from sizes (host-only) ----
    int bigIdx[2] = {0, 1};  int nbig = 0;
    int smallIdx[8] = {0,0,0,0,0,0,0,0}; int nsmall = 0;
    int bcIdx = 2;

    for (int i = 0; i < n_in; i++) {
        if (in_sizes[i] > 100000) {
            if (nbig < 2) bigIdx[nbig] = i;
            nbig++;
        } else if (in_sizes[i] <= 64) {
            if (nsmall < 8) smallIdx[nsmall++] = i;
        } else {
            bcIdx = i;
        }
    }

    const int4* bypass = (const int4*)d_in[bigIdx[0]];
    const int4* prev   = (const int4*)d_in[bigIdx[1]];
    const int*  bc     = (const int*)d_in[bcIdx];

    const int *z1, *z2, *z3, *M1, *M2, *s1, *s2;
    if (in_sizes[0] > 100000) {
        // dict order: z_bypass, z_prev, z3, M0_bypass, M0_prev, shift_bypass, shift_prev
        z1 = (const int*)d_in[smallIdx[0]];
        z2 = (const int*)d_in[smallIdx[1]];
        z3 = (const int*)d_in[smallIdx[2]];
        M1 = (const int*)d_in[smallIdx[3]];
        M2 = (const int*)d_in[smallIdx[4]];
        s1 = (const int*)d_in[smallIdx[5]];
        s2 = (const int*)d_in[smallIdx[6]];
    } else {
        // alphabetical: M0_bypass, M0_prev, shift_bypass, shift_prev, z3, z_bypass, z_prev
        M1 = (const int*)d_in[smallIdx[0]];
        M2 = (const int*)d_in[smallIdx[1]];
        s1 = (const int*)d_in[smallIdx[2]];
        s2 = (const int*)d_in[smallIdx[3]];
        z3 = (const int*)d_in[smallIdx[4]];
        z1 = (const int*)d_in[smallIdx[5]];
        z2 = (const int*)d_in[smallIdx[6]];
    }

    const int B   = in_sizes[bcIdx];               // 128
    const int chw = in_sizes[bigIdx[0]] / B;       // 200704
    const int nv4 = chw / 4;                       // 50176

    dim3 grid(GX, B);                              // 1152 blocks ~ one wave

    qadd_kernel<<<grid, THREADS>>>(bypass, prev, bc, z1, z2, z3, M1, M2, s1, s2,
                                   (float4*)d_out, nv4);
}

// round 7
// speedup vs baseline: 1.0795x; 1.0795x over previous
#include <cuda_runtime.h>

// QuantizedAdd via per-block float shared-memory LUTs (R5 structure, float LUT).
// out = clamp(lut1f[bypass] + lut2f[prev], -128, 127); LUT entries are small
// integers, exact in fp32 -> bit-exact vs reference. Output buffer float32.

#define THREADS 256

__device__ __forceinline__ int rq(int x, int z, int lsh, int M0,
                                  unsigned mask, int thr_base, int rsh)
{
    int d = (x - z) << lsh;
    long long nudge = (d >= 0) ? (1LL << 30) : (1LL - (1LL << 30));
    long long prod = (long long)d * (long long)M0 + nudge;   // IMAD.WIDE
    int v = (int)(prod >> 31);                               // |v| <= 1020
    unsigned rem = (unsigned)v & mask;
    unsigned thr = (unsigned)(thr_base + (v < 0 ? 1 : 0));
    return (v >> rsh) + (rem > thr ? 1 : 0);
}

__global__ void __launch_bounds__(THREADS)
qadd_kernel(const int4* __restrict__ bypass,
            const int4* __restrict__ prev,
            const int* __restrict__ batch_cluster,
            const int* __restrict__ z_bypass,
            const int* __restrict__ z_prev,
            const int* __restrict__ z3_arr,
            const int* __restrict__ M0_bypass,
            const int* __restrict__ M0_prev,
            const int* __restrict__ shift_bypass,
            const int* __restrict__ shift_prev,
            float4* __restrict__ out,
            int nv4)   // (C*H*W)/4 per sample
{
    __shared__ float lut1[256];
    __shared__ float lut2[256];

    const int b = blockIdx.y;
    const int t = threadIdx.x;

    // ---- build LUTs (each thread: one entry per table) ----
    {
        const int c  = __ldg(&batch_cluster[b]);
        const int z1 = __ldg(&z_bypass[c]);
        const int z2 = __ldg(&z_prev[c]);
        const int z3 = __ldg(&z3_arr[c]);
        const int M1 = __ldg(&M0_bypass[c]);
        const int M2 = __ldg(&M0_prev[c]);
        const int s1 = __ldg(&shift_bypass[c]);
        const int s2 = __ldg(&shift_prev[c]);

        const int lsh1 = s1 < 0 ? -s1 : 0;
        const int rsh1 = s1 < 0 ? 0 : s1;
        const int lsh2 = s2 < 0 ? -s2 : 0;
        const int rsh2 = s2 < 0 ? 0 : s2;
        const unsigned mask1 = (1u << rsh1) - 1u;
        const unsigned mask2 = (1u << rsh2) - 1u;

        lut1[t] = (float)(rq(t, z1, lsh1, M1, mask1, (int)(mask1 >> 1), rsh1) + z3);
        lut2[t] = (float)(rq(t, z2, lsh2, M2, mask2, (int)(mask2 >> 1), rsh2));
    }
    __syncthreads();

    const size_t sbase = (size_t)b * (size_t)nv4;
    const int stride = gridDim.x * THREADS;

    for (int i = blockIdx.x * THREADS + t; i < nv4; i += stride) {
        const int4 xb = bypass[sbase + i];
        const int4 xp = prev[sbase + i];

        float4 o;
        o.x = fmaxf(-128.f, fminf(127.f, lut1[xb.x] + lut2[xp.x]));
        o.y = fmaxf(-128.f, fminf(127.f, lut1[xb.y] + lut2[xp.y]));
        o.z = fmaxf(-128.f, fminf(127.f, lut1[xb.z] + lut2[xp.z]));
        o.w = fmaxf(-128.f, fminf(127.f, lut1[xb.w] + lut2[xp.w]));
        out[sbase + i] = o;
    }
}

extern "C" void kernel_launch(void* const* d_in, const int* in_sizes, int n_in,
                              void* d_out, int out_size)
{
    // ---- resolve input mapping from sizes (host-only) ----
    int bigIdx[2] = {0, 1};  int nbig = 0;
    int smallIdx[8] = {0,0,0,0,0,0,0,0}; int nsmall = 0;
    int bcIdx = 2;

    for (int i = 0; i < n_in; i++) {
        if (in_sizes[i] > 100000) {
            if (nbig < 2) bigIdx[nbig] = i;
            nbig++;
        } else if (in_sizes[i] <= 64) {
            if (nsmall < 8) smallIdx[nsmall++] = i;
        } else {
            bcIdx = i;
        }
    }

    const int4* bypass = (const int4*)d_in[bigIdx[0]];
    const int4* prev   = (const int4*)d_in[bigIdx[1]];
    const int*  bc     = (const int*)d_in[bcIdx];

    const int *z1, *z2, *z3, *M1, *M2, *s1, *s2;
    if (in_sizes[0] > 100000) {
        // dict order: z_bypass, z_prev, z3, M0_bypass, M0_prev, shift_bypass, shift_prev
        z1 = (const int*)d_in[smallIdx[0]];
        z2 = (const int*)d_in[smallIdx[1]];
        z3 = (const int*)d_in[smallIdx[2]];
        M1 = (const int*)d_in[smallIdx[3]];
        M2 = (const int*)d_in[smallIdx[4]];
        s1 = (const int*)d_in[smallIdx[5]];
        s2 = (const int*)d_in[smallIdx[6]];
    } else {
        // alphabetical: M0_bypass, M0_prev, shift_bypass, shift_prev, z3, z_bypass, z_prev
        M1 = (const int*)d_in[smallIdx[0]];
        M2 = (const int*)d_in[smallIdx[1]];
        s1 = (const int*)d_in[smallIdx[2]];
        s2 = (const int*)d_in[smallIdx[3]];
        z3 = (const int*)d_in[smallIdx[4]];
        z1 = (const int*)d_in[smallIdx[5]];
        z2 = (const int*)d_in[smallIdx[6]];
    }

    const int B   = in_sizes[bcIdx];               // 128
    const int chw = in_sizes[bigIdx[0]] / B;       // 200704
    const int nv4 = chw / 4;                       // 50176

    int gx = (nv4 + THREADS * 4 - 1) / (THREADS * 4);   // 49 -> 4 iters/thread
    dim3 grid(gx, B);

    qadd_kernel<<<grid, THREADS>>>(bypass, prev, bc, z1, z2, z3, M1, M2, s1, s2,
                                   (float4*)d_out, nv4);
}

// round 8
// speedup vs baseline: 1.1008x; 1.0198x over previous
#include <cuda_runtime.h>

// QuantizedAdd via per-block float shared-memory LUTs (R5/R7 structure).
// This round: exact-trip fully-unrolled main body (nv4 == gx*THREADS*4) so
// ptxas can front-batch all LDG.128s (higher MLP), no loop overhead.
// Output buffer float32; results bit-exact (fp32 sums of small ints).

#define THREADS 256

__device__ __forceinline__ int rq(int x, int z, int lsh, int M0,
                                  unsigned mask, int thr_base, int rsh)
{
    int d = (x - z) << lsh;
    long long nudge = (d >= 0) ? (1LL << 30) : (1LL - (1LL << 30));
    long long prod = (long long)d * (long long)M0 + nudge;   // IMAD.WIDE
    int v = (int)(prod >> 31);                               // |v| <= 1020
    unsigned rem = (unsigned)v & mask;
    unsigned thr = (unsigned)(thr_base + (v < 0 ? 1 : 0));
    return (v >> rsh) + (rem > thr ? 1 : 0);
}

__device__ __forceinline__ void build_luts(
    int b, int t,
    const int* __restrict__ batch_cluster,
    const int* __restrict__ z_bypass, const int* __restrict__ z_prev,
    const int* __restrict__ z3_arr,
    const int* __restrict__ M0_bypass, const int* __restrict__ M0_prev,
    const int* __restrict__ shift_bypass, const int* __restrict__ shift_prev,
    float* lut1, float* lut2)
{
    const int c  = __ldg(&batch_cluster[b]);
    const int z1 = __ldg(&z_bypass[c]);
    const int z2 = __ldg(&z_prev[c]);
    const int z3 = __ldg(&z3_arr[c]);
    const int M1 = __ldg(&M0_bypass[c]);
    const int M2 = __ldg(&M0_prev[c]);
    const int s1 = __ldg(&shift_bypass[c]);
    const int s2 = __ldg(&shift_prev[c]);

    const int lsh1 = s1 < 0 ? -s1 : 0;
    const int rsh1 = s1 < 0 ? 0 : s1;
    const int lsh2 = s2 < 0 ? -s2 : 0;
    const int rsh2 = s2 < 0 ? 0 : s2;
    const unsigned mask1 = (1u << rsh1) - 1u;
    const unsigned mask2 = (1u << rsh2) - 1u;

    lut1[t] = (float)(rq(t, z1, lsh1, M1, mask1, (int)(mask1 >> 1), rsh1) + z3);
    lut2[t] = (float)(rq(t, z2, lsh2, M2, mask2, (int)(mask2 >> 1), rsh2));
}

__device__ __forceinline__ float4 apply_lut(const float* lut1, const float* lut2,
                                            int4 xb, int4 xp)
{
    float4 o;
    o.x = fmaxf(-128.f, fminf(127.f, lut1[xb.x] + lut2[xp.x]));
    o.y = fmaxf(-128.f, fminf(127.f, lut1[xb.y] + lut2[xp.y]));
    o.z = fmaxf(-128.f, fminf(127.f, lut1[xb.z] + lut2[xp.z]));
    o.w = fmaxf(-128.f, fminf(127.f, lut1[xb.w] + lut2[xp.w]));
    return o;
}

template <bool EXACT>
__global__ void __launch_bounds__(THREADS)
qadd_kernel(const int4* __restrict__ bypass,
            const int4* __restrict__ prev,
            const int* __restrict__ batch_cluster,
            const int* __restrict__ z_bypass,
            const int* __restrict__ z_prev,
            const int* __restrict__ z3_arr,
            const int* __restrict__ M0_bypass,
            const int* __restrict__ M0_prev,
            const int* __restrict__ shift_bypass,
            const int* __restrict__ shift_prev,
            float4* __restrict__ out,
            int nv4)   // (C*H*W)/4 per sample
{
    __shared__ float lut1[256];
    __shared__ float lut2[256];

    const int b = blockIdx.y;
    const int t = threadIdx.x;

    build_luts(b, t, batch_cluster, z_bypass, z_prev, z3_arr,
               M0_bypass, M0_prev, shift_bypass, shift_prev, lut1, lut2);
    __syncthreads();

    const size_t sbase = (size_t)b * (size_t)nv4;
    const int stride = gridDim.x * THREADS;
    const int i0 = blockIdx.x * THREADS + t;

    if (EXACT) {
        // exactly 4 iterations per thread, no bounds checks: front-batch loads
        int4 xb[4], xp[4];
        #pragma unroll
        for (int k = 0; k < 4; k++) {
            xb[k] = bypass[sbase + i0 + k * stride];
            xp[k] = prev  [sbase + i0 + k * stride];
        }
        #pragma unroll
        for (int k = 0; k < 4; k++)
            out[sbase + i0 + k * stride] = apply_lut(lut1, lut2, xb[k], xp[k]);
    } else {
        for (int i = i0; i < nv4; i += stride) {
            const int4 xb = bypass[sbase + i];
            const int4 xp = prev[sbase + i];
            out[sbase + i] = apply_lut(lut1, lut2, xb, xp);
        }
    }
}

extern "C" void kernel_launch(void* const* d_in, const int* in_sizes, int n_in,
                              void* d_out, int out_size)
{
    // ---- resolve input mapping from sizes (host-only) ----
    int bigIdx[2] = {0, 1};  int nbig = 0;
    int smallIdx[8] = {0,0,0,0,0,0,0,0}; int nsmall = 0;
    int bcIdx = 2;

    for (int i = 0; i < n_in; i++) {
        if (in_sizes[i] > 100000) {
            if (nbig < 2) bigIdx[nbig] = i;
            nbig++;
        } else if (in_sizes[i] <= 64) {
            if (nsmall < 8) smallIdx[nsmall++] = i;
        } else {
            bcIdx = i;
        }
    }

    const int4* bypass = (const int4*)d_in[bigIdx[0]];
    const int4* prev   = (const int4*)d_in[bigIdx[1]];
    const int*  bc     = (const int*)d_in[bcIdx];

    const int *z1, *z2, *z3, *M1, *M2, *s1, *s2;
    if (in_sizes[0] > 100000) {
        // dict order: z_bypass, z_prev, z3, M0_bypass, M0_prev, shift_bypass, shift_prev
        z1 = (const int*)d_in[smallIdx[0]];
        z2 = (const int*)d_in[smallIdx[1]];
        z3 = (const int*)d_in[smallIdx[2]];
        M1 = (const int*)d_in[smallIdx[3]];
        M2 = (const int*)d_in[smallIdx[4]];
        s1 = (const int*)d_in[smallIdx[5]];
        s2 = (const int*)d_in[smallIdx[6]];
    } else {
        // alphabetical: M0_bypass, M0_prev, shift_bypass, shift_prev, z3, z_bypass, z_prev
        M1 = (const int*)d_in[smallIdx[0]];
        M2 = (const int*)d_in[smallIdx[1]];
        s1 = (const int*)d_in[smallIdx[2]];
        s2 = (const int*)d_in[smallIdx[3]];
        z3 = (const int*)d_in[smallIdx[4]];
        z1 = (const int*)d_in[smallIdx[5]];
        z2 = (const int*)d_in[smallIdx[6]];
    }

    const int B   = in_sizes[bcIdx];               // 128
    const int chw = in_sizes[bigIdx[0]] / B;       // 200704
    const int nv4 = chw / 4;                       // 50176

    int gx = (nv4 + THREADS * 4 - 1) / (THREADS * 4);   // 49
    dim3 grid(gx, B);

    if (gx * THREADS * 4 == nv4) {
        qadd_kernel<true><<<grid, THREADS>>>(bypass, prev, bc, z1, z2, z3,
                                             M1, M2, s1, s2,
                                             (float4*)d_out, nv4);
    } else {
        qadd_kernel<false><<<grid, THREADS>>>(bypass, prev, bc, z1, z2, z3,
                                              M1, M2, s1, s2,
                                              (float4*)d_out, nv4);
    }
}

// round 9
// speedup vs baseline: 1.1058x; 1.0045x over previous
#include <cuda_runtime.h>

// QuantizedAdd via per-block float shared-memory LUTs + 256-bit global accesses
// (Blackwell ld/st.global.v8.b32). Exact-trip: nv8 = gx*THREADS*2 per sample.
// Output buffer float32; bit-exact (fp32 sums of small ints).

#define THREADS 256

__device__ __forceinline__ int rq(int x, int z, int lsh, int M0,
                                  unsigned mask, int thr_base, int rsh)
{
    int d = (x - z) << lsh;
    long long nudge = (d >= 0) ? (1LL << 30) : (1LL - (1LL << 30));
    long long prod = (long long)d * (long long)M0 + nudge;   // IMAD.WIDE
    int v = (int)(prod >> 31);                               // |v| <= 1020
    unsigned rem = (unsigned)v & mask;
    unsigned thr = (unsigned)(thr_base + (v < 0 ? 1 : 0));
    return (v >> rsh) + (rem > thr ? 1 : 0);
}

__device__ __forceinline__ void build_luts(
    int b, int t,
    const int* __restrict__ batch_cluster,
    const int* __restrict__ z_bypass, const int* __restrict__ z_prev,
    const int* __restrict__ z3_arr,
    const int* __restrict__ M0_bypass, const int* __restrict__ M0_prev,
    const int* __restrict__ shift_bypass, const int* __restrict__ shift_prev,
    float* lut1, float* lut2)
{
    const int c  = __ldg(&batch_cluster[b]);
    const int z1 = __ldg(&z_bypass[c]);
    const int z2 = __ldg(&z_prev[c]);
    const int z3 = __ldg(&z3_arr[c]);
    const int M1 = __ldg(&M0_bypass[c]);
    const int M2 = __ldg(&M0_prev[c]);
    const int s1 = __ldg(&shift_bypass[c]);
    const int s2 = __ldg(&shift_prev[c]);

    const int lsh1 = s1 < 0 ? -s1 : 0;
    const int rsh1 = s1 < 0 ? 0 : s1;
    const int lsh2 = s2 < 0 ? -s2 : 0;
    const int rsh2 = s2 < 0 ? 0 : s2;
    const unsigned mask1 = (1u << rsh1) - 1u;
    const unsigned mask2 = (1u << rsh2) - 1u;

    lut1[t] = (float)(rq(t, z1, lsh1, M1, mask1, (int)(mask1 >> 1), rsh1) + z3);
    lut2[t] = (float)(rq(t, z2, lsh2, M2, mask2, (int)(mask2 >> 1), rsh2));
}

// ---- 256-bit global access helpers (sm_100+/sm_103a) ----
__device__ __forceinline__ void ldg256(const int* p, int* r)
{
    asm volatile("ld.global.nc.v8.b32 {%0,%1,%2,%3,%4,%5,%6,%7}, [%8];"
                 : "=r"(r[0]), "=r"(r[1]), "=r"(r[2]), "=r"(r[3]),
                   "=r"(r[4]), "=r"(r[5]), "=r"(r[6]), "=r"(r[7])
                 : "l"(p));
}

__device__ __forceinline__ void stg256(float* p, const float* v)
{
    asm volatile("st.global.v8.b32 [%0], {%1,%2,%3,%4,%5,%6,%7,%8};"
                 :: "l"(p),
                    "f"(v[0]), "f"(v[1]), "f"(v[2]), "f"(v[3]),
                    "f"(v[4]), "f"(v[5]), "f"(v[6]), "f"(v[7])
                 : "memory");
}

template <bool EXACT>
__global__ void __launch_bounds__(THREADS)
qadd_kernel(const int* __restrict__ bypass,
            const int* __restrict__ prev,
            const int* __restrict__ batch_cluster,
            const int* __restrict__ z_bypass,
            const int* __restrict__ z_prev,
            const int* __restrict__ z3_arr,
            const int* __restrict__ M0_bypass,
            const int* __restrict__ M0_prev,
            const int* __restrict__ shift_bypass,
            const int* __restrict__ shift_prev,
            float* __restrict__ out,
            int nv8)   // (C*H*W)/8 per sample
{
    __shared__ float lut1[256];
    __shared__ float lut2[256];

    const int b = blockIdx.y;
    const int t = threadIdx.x;

    build_luts(b, t, batch_cluster, z_bypass, z_prev, z3_arr,
               M0_bypass, M0_prev, shift_bypass, shift_prev, lut1, lut2);
    __syncthreads();

    const size_t sbase = (size_t)b * (size_t)nv8 * 8;   // element base of sample
    const int stride = gridDim.x * THREADS;             // in v8 units
    const int j0 = blockIdx.x * THREADS + t;

    if (EXACT) {
        // exactly 2 v8-chunks per thread
        #pragma unroll
        for (int k = 0; k < 2; k++) {
            const size_t e = sbase + (size_t)(j0 + k * stride) * 8;
            int xb[8], xp[8];
            ldg256(&bypass[e], xb);
            ldg256(&prev[e],   xp);
            float o[8];
            #pragma unroll
            for (int m = 0; m < 8; m++)
                o[m] = fmaxf(-128.f, fminf(127.f, lut1[xb[m]] + lut2[xp[m]]));
            stg256(&out[e], o);
        }
    } else {
        for (int j = j0; j < nv8; j += stride) {
            const size_t e = sbase + (size_t)j * 8;
            int xb[8], xp[8];
            ldg256(&bypass[e], xb);
            ldg256(&prev[e],   xp);
            float o[8];
            #pragma unroll
            for (int m = 0; m < 8; m++)
                o[m] = fmaxf(-128.f, fminf(127.f, lut1[xb[m]] + lut2[xp[m]]));
            stg256(&out[e], o);
        }
    }
}

extern "C" void kernel_launch(void* const* d_in, const int* in_sizes, int n_in,
                              void* d_out, int out_size)
{
    // ---- resolve input mapping from sizes (host-only) ----
    int bigIdx[2] = {0, 1};  int nbig = 0;
    int smallIdx[8] = {0,0,0,0,0,0,0,0}; int nsmall = 0;
    int bcIdx = 2;

    for (int i = 0; i < n_in; i++) {
        if (in_sizes[i] > 100000) {
            if (nbig < 2) bigIdx[nbig] = i;
            nbig++;
        } else if (in_sizes[i] <= 64) {
            if (nsmall < 8) smallIdx[nsmall++] = i;
        } else {
            bcIdx = i;
        }
    }

    const int* bypass = (const int*)d_in[bigIdx[0]];
    const int* prev   = (const int*)d_in[bigIdx[1]];
    const int* bc     = (const int*)d_in[bcIdx];

    const int *z1, *z2, *z3, *M1, *M2, *s1, *s2;
    if (in_sizes[0] > 100000) {
        // dict order: z_bypass, z_prev, z3, M0_bypass, M0_prev, shift_bypass, shift_prev
        z1 = (const int*)d_in[smallIdx[0]];
        z2 = (const int*)d_in[smallIdx[1]];
        z3 = (const int*)d_in[smallIdx[2]];
        M1 = (const int*)d_in[smallIdx[3]];
        M2 = (const int*)d_in[smallIdx[4]];
        s1 = (const int*)d_in[smallIdx[5]];
        s2 = (const int*)d_in[smallIdx[6]];
    } else {
        // alphabetical: M0_bypass, M0_prev, shift_bypass, shift_prev, z3, z_bypass, z_prev
        M1 = (const int*)d_in[smallIdx[0]];
        M2 = (const int*)d_in[smallIdx[1]];
        s1 = (const int*)d_in[smallIdx[2]];
        s2 = (const int*)d_in[smallIdx[3]];
        z3 = (const int*)d_in[smallIdx[4]];
        z1 = (const int*)d_in[smallIdx[5]];
        z2 = (const int*)d_in[smallIdx[6]];
    }

    const int B   = in_sizes[bcIdx];               // 128
    const int chw = in_sizes[bigIdx[0]] / B;       // 200704
    const int nv8 = chw / 8;                       // 25088 = 49*256*2

    int gx = (nv8 + THREADS * 2 - 1) / (THREADS * 2);   // 49
    dim3 grid(gx, B);

    if (gx * THREADS * 2 == nv8) {
        qadd_kernel<true><<<grid, THREADS>>>(bypass, prev, bc, z1, z2, z3,
                                             M1, M2, s1, s2,
                                             (float*)d_out, nv8);
    } else {
        qadd_kernel<false><<<grid, THREADS>>>(bypass, prev, bc, z1, z2, z3,
                                              M1, M2, s1, s2,
                                              (float*)d_out, nv8);
    }
}